// round 1
// baseline (speedup 1.0000x reference)
#include <cuda_runtime.h>
#include <cuda_bf16.h>

// ---------------- problem constants ----------------
#define HID 64
#define INDIM 4800
#define DEPTH 14
#define NNODES 16383          // 2^14 - 1
#define NGEMM 256             // 4*HID

// ---------------- scratch (device globals; no allocation allowed) ----------
__device__ float g_Wx[NNODES * NGEMM];     // [node][i|f|o|u] gate pre-activations
__device__ float g_h[NNODES * HID];
__device__ float g_c[NNODES * HID];
__device__ float g_Uit[HID * HID];         // Ut[h*64+o] = U[o*64+h]
__device__ float g_Uft[HID * HID];
__device__ float g_Uot[HID * HID];
__device__ float g_Uut[HID * HID];
__device__ float g_convWt[2 * HID * HID];  // [ (k*64+h) * 64 + o ] = convW[o,k,h]
__device__ float g_v[3 * HID];             // leaf constants: conv_b @ U_{i,o,u}.T

// ---------------- helpers ----------------
__device__ __forceinline__ float sigmoidf_(float x) { return 1.f / (1.f + __expf(-x)); }

__device__ __forceinline__ unsigned f2tf32(float x) {
    unsigned r;
    asm("cvt.rna.tf32.f32 %0, %1;" : "=r"(r) : "f"(x));
    return r;
}

__device__ __forceinline__ void mma_tf32(float* d, const unsigned* a, const unsigned* b) {
    asm volatile(
        "mma.sync.aligned.m16n8k8.row.col.f32.tf32.tf32.f32 "
        "{%0,%1,%2,%3},{%4,%5,%6,%7},{%8,%9},{%0,%1,%2,%3};"
        : "+f"(d[0]), "+f"(d[1]), "+f"(d[2]), "+f"(d[3])
        : "r"(a[0]), "r"(a[1]), "r"(a[2]), "r"(a[3]), "r"(b[0]), "r"(b[1]));
}

__device__ __forceinline__ void cp_async16(float* smem_dst, const float* gsrc) {
    unsigned sa = (unsigned)__cvta_generic_to_shared(smem_dst);
    asm volatile("cp.async.cg.shared.global [%0], [%1], 16;\n" :: "r"(sa), "l"(gsrc));
}
__device__ __forceinline__ void cp_commit() { asm volatile("cp.async.commit_group;\n"); }
__device__ __forceinline__ void cp_wait1() { asm volatile("cp.async.wait_group 1;\n"); }

// ---------------- GEMM: Wx = inputs @ Wx_w.T + Wx_b  (tf32 MMA) ----------
#define BM 128
#define BN 128
#define BK 32
#define PADK 36                 // BK + 4: conflict-free 32-bit frag loads
#define STAGE_F (BM * PADK)     // floats per A stage (== per B stage)
#define GEMM_SMEM_BYTES (4 * STAGE_F * sizeof(float))  // 2 A stages + 2 B stages

__global__ void __launch_bounds__(256)
gemm_kernel(const float* __restrict__ A,      // [NNODES, INDIM]
            const float* __restrict__ B,      // [NGEMM, INDIM]
            const float* __restrict__ bias)   // [NGEMM]
{
    extern __shared__ float smem[];
    float* sA = smem;                 // [2][BM][PADK]
    float* sB = smem + 2 * STAGE_F;   // [2][BN][PADK]

    const int tid  = threadIdx.x;
    const int lane = tid & 31;
    const int warp = tid >> 5;
    const int wm = warp >> 1;         // 0..3
    const int wn = warp & 1;          // 0..1
    const int m0 = wm * 32;
    const int n0 = wn * 64;
    const int bm = blockIdx.y * BM;
    const int bn = blockIdx.x * BN;

    float acc[2][8][4];
#pragma unroll
    for (int i = 0; i < 2; ++i)
#pragma unroll
        for (int j = 0; j < 8; ++j)
#pragma unroll
            for (int k = 0; k < 4; ++k) acc[i][j][k] = 0.f;

    auto load_tiles = [&](int stage, int k0) {
#pragma unroll
        for (int i = 0; i < 4; ++i) {
            int idx = tid + i * 256;          // 0..1023
            int row = idx >> 3;               // 0..127
            int c4  = idx & 7;                // 0..7 (float4 within row)
            int gr = bm + row;
            if (gr >= NNODES) gr = NNODES - 1;   // clamp (row never stored)
            cp_async16(&sA[stage * STAGE_F + row * PADK + c4 * 4],
                       A + (size_t)gr * INDIM + k0 + c4 * 4);
            cp_async16(&sB[stage * STAGE_F + row * PADK + c4 * 4],
                       B + (size_t)(bn + row) * INDIM + k0 + c4 * 4);
        }
    };

    const int nk = INDIM / BK;   // 150
    load_tiles(0, 0);
    cp_commit();

    for (int kt = 0; kt < nk; ++kt) {
        if (kt + 1 < nk) load_tiles((kt + 1) & 1, (kt + 1) * BK);
        cp_commit();
        cp_wait1();
        __syncthreads();

        const float* tA = sA + (kt & 1) * STAGE_F;
        const float* tB = sB + (kt & 1) * STAGE_F;
        const int r  = lane >> 2;
        const int cc = lane & 3;

#pragma unroll
        for (int ks = 0; ks < 4; ++ks) {
            const int kcol = ks * 8;
            unsigned af[2][4], bf[8][2];
#pragma unroll
            for (int im = 0; im < 2; ++im) {
                const float* base = tA + (m0 + im * 16 + r) * PADK + kcol + cc;
                af[im][0] = f2tf32(base[0]);
                af[im][1] = f2tf32(base[8 * PADK]);
                af[im][2] = f2tf32(base[4]);
                af[im][3] = f2tf32(base[8 * PADK + 4]);
            }
#pragma unroll
            for (int in = 0; in < 8; ++in) {
                const float* bb = tB + (n0 + in * 8 + r) * PADK + kcol + cc;
                bf[in][0] = f2tf32(bb[0]);
                bf[in][1] = f2tf32(bb[4]);
            }
#pragma unroll
            for (int im = 0; im < 2; ++im)
#pragma unroll
                for (int in = 0; in < 8; ++in)
                    mma_tf32(acc[im][in], af[im], bf[in]);
        }
        __syncthreads();
    }

    // epilogue: add bias, store to g_Wx
#pragma unroll
    for (int im = 0; im < 2; ++im) {
#pragma unroll
        for (int in = 0; in < 8; ++in) {
            int rr  = bm + m0 + im * 16 + (lane >> 2);
            int ccg = bn + n0 + in * 8 + (lane & 3) * 2;
            float b0 = bias[ccg], b1 = bias[ccg + 1];
            if (rr < NNODES) {
                g_Wx[(size_t)rr * NGEMM + ccg]     = acc[im][in][0] + b0;
                g_Wx[(size_t)rr * NGEMM + ccg + 1] = acc[im][in][1] + b1;
            }
            int rr2 = rr + 8;
            if (rr2 < NNODES) {
                g_Wx[(size_t)rr2 * NGEMM + ccg]     = acc[im][in][2] + b0;
                g_Wx[(size_t)rr2 * NGEMM + ccg + 1] = acc[im][in][3] + b1;
            }
        }
    }
}

// ---------------- prep: transpose weights, leaf constants ----------------
__global__ void prep_kernel(const float* __restrict__ U_i, const float* __restrict__ U_f,
                            const float* __restrict__ U_o, const float* __restrict__ U_u,
                            const float* __restrict__ convW, const float* __restrict__ conv_b)
{
    int t = threadIdx.x;
    for (int idx = t; idx < HID * HID; idx += 256) {
        int o = idx >> 6, h = idx & 63;
        g_Uit[h * HID + o] = U_i[idx];
        g_Uft[h * HID + o] = U_f[idx];
        g_Uot[h * HID + o] = U_o[idx];
        g_Uut[h * HID + o] = U_u[idx];
    }
    for (int idx = t; idx < 2 * HID * HID; idx += 256) {
        int o = idx >> 7, kh = idx & 127;
        g_convWt[kh * HID + o] = convW[idx];
    }
    if (t < HID) {
        float vi = 0.f, vo = 0.f, vu = 0.f;
        for (int h = 0; h < HID; ++h) {
            float b = conv_b[h];
            vi += b * U_i[t * HID + h];
            vo += b * U_o[t * HID + h];
            vu += b * U_u[t * HID + h];
        }
        g_v[t] = vi; g_v[HID + t] = vo; g_v[2 * HID + t] = vu;
    }
}

// ---------------- leaves (level d = DEPTH-1): avg == conv_b, sum_f == 0 ----
__global__ void leaf_kernel()
{
    int idx = blockIdx.x * blockDim.x + threadIdx.x;  // 8192*64 threads
    int o = idx & 63;
    int node = (1 << (DEPTH - 1)) - 1 + (idx >> 6);   // 8191 + local
    const float* wx = g_Wx + (size_t)node * NGEMM;
    float zi = wx[o]        + g_v[o];
    float zo = wx[128 + o]  + g_v[HID + o];
    float zu = wx[192 + o]  + g_v[2 * HID + o];
    float iv = sigmoidf_(zi);
    float ov = sigmoidf_(zo);
    float uv = tanhf(zu);
    float c  = iv * uv;
    g_c[(size_t)node * HID + o] = c;
    g_h[(size_t)node * HID + o] = ov * tanhf(c);
}

// ---------------- one inner level (4 nodes / block of 256) ----------------
__device__ __forceinline__ void process_node(int node, int g, int o,
                                             float (*sh)[128], float (*sc)[128], float (*sa)[64],
                                             const float* __restrict__ conv_b, bool act)
{
    float sumf = 0.f;
    if (act) {
        int base = (2 * node + 1) * HID;   // left child; right is contiguous
        sh[g][o]      = g_h[base + o];
        sh[g][64 + o] = g_h[base + 64 + o];
        sc[g][o]      = g_c[base + o];
        sc[g][64 + o] = g_c[base + 64 + o];
    }
    __syncthreads();
    if (act) {
        float avg = conv_b[o];
#pragma unroll 8
        for (int h = 0; h < 128; ++h) avg += sh[g][h] * g_convWt[h * HID + o];
        sa[g][o] = avg;
        float xf = g_Wx[(size_t)node * NGEMM + 64 + o];
        float f0 = xf, f1 = xf;
#pragma unroll 8
        for (int h = 0; h < HID; ++h) {
            float u = g_Uft[h * HID + o];
            f0 += sh[g][h] * u;
            f1 += sh[g][64 + h] * u;
        }
        sumf = sigmoidf_(f0) * sc[g][o] + sigmoidf_(f1) * sc[g][64 + o];
    }
    __syncthreads();
    if (act) {
        const float* wx = g_Wx + (size_t)node * NGEMM;
        float zi = wx[o], zo = wx[128 + o], zu = wx[192 + o];
#pragma unroll 8
        for (int h = 0; h < HID; ++h) {
            float a = sa[g][h];
            zi += a * g_Uit[h * HID + o];
            zo += a * g_Uot[h * HID + o];
            zu += a * g_Uut[h * HID + o];
        }
        float iv = sigmoidf_(zi);
        float ov = sigmoidf_(zo);
        float uv = tanhf(zu);
        float c  = sumf + iv * uv;
        g_c[(size_t)node * HID + o] = c;
        g_h[(size_t)node * HID + o] = ov * tanhf(c);
    }
    __syncthreads();
}

__global__ void level_kernel(const float* __restrict__ conv_b, int start, int n)
{
    __shared__ float sh[4][128], sc[4][128], sa[4][64];
    int g = threadIdx.x >> 6, o = threadIdx.x & 63;
    int j = blockIdx.x * 4 + g;
    process_node(start + j, g, o, sh, sc, sa, conv_b, j < n);
}

// ---------------- fused top levels d = 5..0 (single block) + output -------
__global__ void __launch_bounds__(1024)
top_levels_kernel(const float* __restrict__ conv_b, float* __restrict__ out)
{
    __shared__ float sh[16][128], sc[16][128], sa[16][64];
    int g = threadIdx.x >> 6, o = threadIdx.x & 63;
    for (int d = 5; d >= 0; --d) {
        int n = 1 << d, start = n - 1;
        for (int jb = 0; jb < n; jb += 16) {
            int j = jb + g;
            process_node(start + j, g, o, sh, sc, sa, conv_b, j < n);
        }
    }
    if (threadIdx.x < HID) {
        out[threadIdx.x]       = g_h[threadIdx.x];   // root h
        out[HID + threadIdx.x] = g_c[threadIdx.x];   // root c
    }
}

// ---------------- launch ----------------
extern "C" void kernel_launch(void* const* d_in, const int* in_sizes, int n_in,
                              void* d_out, int out_size)
{
    const float* inputs = (const float*)d_in[0];
    const float* Wx_w   = (const float*)d_in[1];
    const float* Wx_b   = (const float*)d_in[2];
    const float* U_i    = (const float*)d_in[3];
    const float* U_f    = (const float*)d_in[4];
    const float* U_o    = (const float*)d_in[5];
    const float* U_u    = (const float*)d_in[6];
    const float* convW  = (const float*)d_in[7];
    const float* conv_b = (const float*)d_in[8];
    float* out = (float*)d_out;

    cudaFuncSetAttribute(gemm_kernel, cudaFuncAttributeMaxDynamicSharedMemorySize,
                         (int)GEMM_SMEM_BYTES);

    prep_kernel<<<1, 256>>>(U_i, U_f, U_o, U_u, convW, conv_b);

    dim3 ggrid(NGEMM / BN, (NNODES + BM - 1) / BM);   // (2, 128)
    gemm_kernel<<<ggrid, 256, GEMM_SMEM_BYTES>>>(inputs, Wx_w, Wx_b);

    leaf_kernel<<<(1 << (DEPTH - 1)) * HID / 256, 256>>>();   // 2048 blocks

    for (int d = DEPTH - 2; d >= 6; --d) {
        int n = 1 << d;
        level_kernel<<<(n + 3) / 4, 256>>>(conv_b, n - 1, n);
    }
    top_levels_kernel<<<1, 1024>>>(conv_b, out);
}